// round 12
// baseline (speedup 1.0000x reference)
#include <cuda_runtime.h>
#include <cstdint>

#define OLD_SR 4
#define NEW_SR 5
#define KSZ    56            // taps per phase
#define WIDTH  26            // left pad (edge replicate)
#define THREADS 256
#define NPT    2             // consecutive n's per thread
#define NTILE  (THREADS * NPT)          // 512 n per tile
#define NLOAD  (OLD_SR * NTILE + KSZ)   // 2104 staged floats (= 526 x 16B units)
#define HSZ    1056          // per-parity array size (263 units*4 floats, padded)
#define NCTAS  740           // 148 SMs x 5 resident CTAs (regs=48 -> 5/SM)
#define TPR    512           // tiles per row
#define NTT    (32 * TPR)    // 16384 tiles total

// ---------------------------------------------------------------------------
// Compile-time polyphase table (double-only constexpr; (float) cast at the
// use site folds to a float literal -> SASS FFMA R,R,IMM,R, rt_SMSP=1).
// ---------------------------------------------------------------------------
constexpr double D_PI      = 3.141592653589793;
constexpr double TWO_OV_PI = 0.6366197723675814;
constexpr double PIO2_HI   = 1.5707963267948966;
constexpr double PIO2_LO   = 6.123233995736766e-17;

constexpr double poly_sin(double y) {
    double y2 = y * y;
    return y * (1.0 + y2 * (-1.0/6 + y2 * (1.0/120 + y2 * (-1.0/5040
             + y2 * (1.0/362880 + y2 * (-1.0/39916800
             + y2 * (1.0/6227020800.0 - y2 * (1.0/1307674368000.0))))))));
}
constexpr double poly_cos(double y) {
    double y2 = y * y;
    return 1.0 + y2 * (-0.5 + y2 * (1.0/24 + y2 * (-1.0/720
             + y2 * (1.0/40320 + y2 * (-1.0/3628800
             + y2 * (1.0/479001600.0 - y2 * (1.0/87178291200.0)))))));
}
constexpr int red_m(double x, double& y) {
    double q = x * TWO_OV_PI;
    int k = (int)(q + (q >= 0 ? 0.5 : -0.5));
    y = (x - k * PIO2_HI) - k * PIO2_LO;
    int m = k % 4; if (m < 0) m += 4;
    return m;
}
constexpr double ksin(double x) {
    double y = 0.0; int m = red_m(x, y);
    return (m == 0) ? poly_sin(y) : (m == 1) ? poly_cos(y)
         : (m == 2) ? -poly_sin(y) : -poly_cos(y);
}
constexpr double kcos(double x) {
    double y = 0.0; int m = red_m(x, y);
    return (m == 0) ? poly_cos(y) : (m == 1) ? -poly_sin(y)
         : (m == 2) ? -poly_cos(y) : poly_sin(y);
}
struct KTabD {
    double c[NEW_SR][KSZ];
    constexpr KTabD() : c{} {
        for (int i = 0; i < NEW_SR; ++i) {
            double s = 0.0;
            for (int j = 0; j < KSZ; ++j) {
                double t = (-(double)i / 5.0 + (double)(j - WIDTH) / 4.0)
                         * (4.0 * 0.945);
                if (t > 24.0) t = 24.0;
                if (t < -24.0) t = -24.0;
                t *= D_PI;
                double snc = (t == 0.0) ? 1.0 : ksin(t) / t;
                double w = kcos(t / 48.0);
                double v = snc * w * w;
                c[i][j] = v; s += v;
            }
            for (int j = 0; j < KSZ; ++j) c[i][j] = c[i][j] / s;
        }
    }
};

__global__ __launch_bounds__(THREADS, 5)
void resample_kernel(const float* __restrict__ x,
                     float* __restrict__ out, int T)
{
    constexpr KTabD KT{};
    // [buf][parity][..]: parity 0 holds even 16B units, parity 1 odd units.
    __shared__ __align__(16) float sx[2][2][HSZ];

    const int tid = threadIdx.x;
    const size_t Orow = (size_t)NEW_SR * (size_t)(T / OLD_SR);

    auto stage_to_regs = [&](int tile, float r[9]) {
        const int b   = tile >> 9;               // TPR = 512
        const int tir = tile & (TPR - 1);
        const float* xrow = x + (size_t)b * (size_t)T;
        const int base_j = OLD_SR * (tir * NTILE) - WIDTH;
        if (tir != 0 && tir != TPR - 1) {
            #pragma unroll
            for (int k = 0; k < 9; ++k) {
                int idx = tid + THREADS * k;
                if (idx < NLOAD) r[k] = xrow[base_j + idx];   // no clamps
            }
        } else {
            #pragma unroll
            for (int k = 0; k < 9; ++k) {
                int idx = tid + THREADS * k;
                if (idx < NLOAD) {
                    int j = base_j + idx;
                    j = j < 0 ? 0 : (j > T - 1 ? T - 1 : j);
                    r[k] = xrow[j];
                }
            }
        }
    };
    // De-interleave by unit parity: unit u = idx>>2 goes to [u&1] at
    // position (u>>1)*4 + (idx&3). Linear, cheap, conflict-free on read.
    auto commit_to_smem = [&](int buf, const float r[9]) {
        #pragma unroll
        for (int k = 0; k < 9; ++k) {
            int idx = tid + THREADS * k;
            if (idx < NLOAD) {
                int u   = idx >> 2;
                int pos = ((u >> 1) << 2) | (idx & 3);
                sx[buf][u & 1][pos] = r[k];
            }
        }
    };

    int tile = blockIdx.x;
    {
        float r[9];
        stage_to_regs(tile, r);
        commit_to_smem(0, r);
    }
    __syncthreads();

    int it = 0;
    #pragma unroll 1
    for (; tile < NTT; tile += NCTAS, ++it) {
        // ---- prefetch next tile into registers (overlaps the FFMAs) ----
        float r[9];
        const int next = tile + NCTAS;
        if (next < NTT) stage_to_regs(next, r);

        // ---- compute 2 consecutive n's: 15 quads feed both windows ----
        // Thread window = units 2t..2t+14; quad q: even -> E[t+q/2],
        // odd -> O[t+(q-1)/2]. Fixed q => lanes read consecutive float4s:
        // conflict-free, and offsets fold to immediates.
        float a0[NEW_SR] = {0.f,0.f,0.f,0.f,0.f};
        float a1[NEW_SR] = {0.f,0.f,0.f,0.f,0.f};
        const float4* e4 = reinterpret_cast<const float4*>(&sx[it & 1][0][0]) + tid;
        const float4* o4 = reinterpret_cast<const float4*>(&sx[it & 1][1][0]) + tid;
        #pragma unroll
        for (int q = 0; q <= 14; ++q) {
            const float4 xv = (q & 1) ? o4[(q - 1) >> 1] : e4[q >> 1];
            const float e0 = xv.x, e1 = xv.y, e2 = xv.z, e3 = xv.w;
            if (q <= 13) {           // n0: taps 4q..4q+3
                #pragma unroll
                for (int i = 0; i < NEW_SR; ++i) {
                    if ((float)KT.c[i][4*q+0] != 0.0f) a0[i] = fmaf(e0, (float)KT.c[i][4*q+0], a0[i]);
                    if ((float)KT.c[i][4*q+1] != 0.0f) a0[i] = fmaf(e1, (float)KT.c[i][4*q+1], a0[i]);
                    if ((float)KT.c[i][4*q+2] != 0.0f) a0[i] = fmaf(e2, (float)KT.c[i][4*q+2], a0[i]);
                    if ((float)KT.c[i][4*q+3] != 0.0f) a0[i] = fmaf(e3, (float)KT.c[i][4*q+3], a0[i]);
                }
            }
            if (q >= 1) {            // n1 = n0+1: taps 4(q-1)..4(q-1)+3
                const int p = 4 * (q - 1);
                #pragma unroll
                for (int i = 0; i < NEW_SR; ++i) {
                    if ((float)KT.c[i][p+0] != 0.0f) a1[i] = fmaf(e0, (float)KT.c[i][p+0], a1[i]);
                    if ((float)KT.c[i][p+1] != 0.0f) a1[i] = fmaf(e1, (float)KT.c[i][p+1], a1[i]);
                    if ((float)KT.c[i][p+2] != 0.0f) a1[i] = fmaf(e2, (float)KT.c[i][p+2], a1[i]);
                    if ((float)KT.c[i][p+3] != 0.0f) a1[i] = fmaf(e3, (float)KT.c[i][p+3], a1[i]);
                }
            }
        }

        // ---- store 10 contiguous floats (8B-aligned) as 5 STG.64 ----
        {
            const int b   = tile >> 9;
            const int tir = tile & (TPR - 1);
            const int n0  = tir * NTILE + NPT * tid;
            float2* o = reinterpret_cast<float2*>(
                out + (size_t)b * Orow + (size_t)NEW_SR * (size_t)n0);
            o[0] = make_float2(a0[0], a0[1]);
            o[1] = make_float2(a0[2], a0[3]);
            o[2] = make_float2(a0[4], a1[0]);
            o[3] = make_float2(a1[1], a1[2]);
            o[4] = make_float2(a1[3], a1[4]);
        }

        // ---- commit prefetch to the other buffer; one sync per tile ----
        if (next < NTT) {
            commit_to_smem((it + 1) & 1, r);
            __syncthreads();
        }
    }
}

extern "C" void kernel_launch(void* const* d_in, const int* in_sizes, int n_in,
                              void* d_out, int out_size)
{
    const float* x = (const float*)d_in[0];
    int xs = in_sizes[0];
    // Defensive: if input order is (kernel, x), swap (coeffs are baked in).
    if (n_in >= 2 && in_sizes[0] == NEW_SR * KSZ) {
        x  = (const float*)d_in[1];
        xs = in_sizes[1];
    }
    const int B = 32;
    const int T = xs / B;     // 1048576
    resample_kernel<<<NCTAS, THREADS>>>(x, (float*)d_out, T);
}

// round 13
// speedup vs baseline: 1.1282x; 1.1282x over previous
#include <cuda_runtime.h>
#include <cstdint>

#define OLD_SR 4
#define NEW_SR 5
#define KSZ    56            // taps per phase
#define WIDTH  26            // left pad (edge replicate)
#define THREADS 256
#define NWARPS 8
#define WN     32            // n-groups per warp-tile
#define WLOAD  (OLD_SR * WN + KSZ)   // 184 staged floats per warp-tile
#define WBUF   192           // padded per-buffer size (floats)
#define NCTAS  888           // 148 SMs x 6 CTAs (regs<=40)
#define NW     (NCTAS * NWARPS)      // 7104 concurrent warp streams
#define TPW    8192          // warp-tiles per row = 262144 / 32
#define NTT    (32 * TPW)    // 262144 warp-tiles total

// ---------------------------------------------------------------------------
// Compile-time polyphase table (double-only constexpr; (float) cast at the
// use site folds to a float literal -> SASS FFMA R,R,IMM,R, rt_SMSP=1).
// ---------------------------------------------------------------------------
constexpr double D_PI      = 3.141592653589793;
constexpr double TWO_OV_PI = 0.6366197723675814;
constexpr double PIO2_HI   = 1.5707963267948966;
constexpr double PIO2_LO   = 6.123233995736766e-17;

constexpr double poly_sin(double y) {
    double y2 = y * y;
    return y * (1.0 + y2 * (-1.0/6 + y2 * (1.0/120 + y2 * (-1.0/5040
             + y2 * (1.0/362880 + y2 * (-1.0/39916800
             + y2 * (1.0/6227020800.0 - y2 * (1.0/1307674368000.0))))))));
}
constexpr double poly_cos(double y) {
    double y2 = y * y;
    return 1.0 + y2 * (-0.5 + y2 * (1.0/24 + y2 * (-1.0/720
             + y2 * (1.0/40320 + y2 * (-1.0/3628800
             + y2 * (1.0/479001600.0 - y2 * (1.0/87178291200.0)))))));
}
constexpr int red_m(double x, double& y) {
    double q = x * TWO_OV_PI;
    int k = (int)(q + (q >= 0 ? 0.5 : -0.5));
    y = (x - k * PIO2_HI) - k * PIO2_LO;
    int m = k % 4; if (m < 0) m += 4;
    return m;
}
constexpr double ksin(double x) {
    double y = 0.0; int m = red_m(x, y);
    return (m == 0) ? poly_sin(y) : (m == 1) ? poly_cos(y)
         : (m == 2) ? -poly_sin(y) : -poly_cos(y);
}
constexpr double kcos(double x) {
    double y = 0.0; int m = red_m(x, y);
    return (m == 0) ? poly_cos(y) : (m == 1) ? -poly_sin(y)
         : (m == 2) ? -poly_cos(y) : poly_sin(y);
}
struct KTabD {
    double c[NEW_SR][KSZ];
    constexpr KTabD() : c{} {
        for (int i = 0; i < NEW_SR; ++i) {
            double s = 0.0;
            for (int j = 0; j < KSZ; ++j) {
                double t = (-(double)i / 5.0 + (double)(j - WIDTH) / 4.0)
                         * (4.0 * 0.945);
                if (t > 24.0) t = 24.0;
                if (t < -24.0) t = -24.0;
                t *= D_PI;
                double snc = (t == 0.0) ? 1.0 : ksin(t) / t;
                double w = kcos(t / 48.0);
                double v = snc * w * w;
                c[i][j] = v; s += v;
            }
            for (int j = 0; j < KSZ; ++j) c[i][j] = c[i][j] / s;
        }
    }
};

__global__ __launch_bounds__(THREADS, 6)
void resample_kernel(const float* __restrict__ x,
                     float* __restrict__ out, int T)
{
    constexpr KTabD KT{};
    // Per-warp private double buffer: no cross-warp synchronization at all.
    __shared__ __align__(16) float sw[NWARPS][2][WBUF];

    const int lane = threadIdx.x & 31;
    const int wid  = threadIdx.x >> 5;
    const size_t Orow = (size_t)NEW_SR * (size_t)(T / OLD_SR);

    // Warp-tile walk: global warp stream id, stride NW.
    int wt = blockIdx.x * NWARPS + wid;

    auto stage_to_regs = [&](int t, float r[6]) {
        const int b  = t >> 13;                  // TPW = 8192
        const int tw = t & (TPW - 1);
        const float* xrow = x + (size_t)b * (size_t)T;
        const int base_j = OLD_SR * WN * tw - WIDTH;
        if (tw != 0 && tw != TPW - 1) {          // interior: no clamps
            #pragma unroll
            for (int k = 0; k < 6; ++k) {
                int idx = lane + 32 * k;
                if (idx < WLOAD) r[k] = xrow[base_j + idx];
            }
        } else {                                  // row edges: clamp
            #pragma unroll
            for (int k = 0; k < 6; ++k) {
                int idx = lane + 32 * k;
                if (idx < WLOAD) {
                    int j = base_j + idx;
                    j = j < 0 ? 0 : (j > T - 1 ? T - 1 : j);
                    r[k] = xrow[j];
                }
            }
        }
    };
    auto commit = [&](int buf, const float r[6]) {
        #pragma unroll
        for (int k = 0; k < 6; ++k) {
            int idx = lane + 32 * k;
            if (idx < WLOAD) sw[wid][buf][idx] = r[k];
        }
    };

    if (wt < NTT) {
        float r[6];
        stage_to_regs(wt, r);
        commit(0, r);
    }
    __syncwarp();

    int cur = 0;
    #pragma unroll 1
    for (; wt < NTT; wt += NW, cur ^= 1) {
        // ---- prefetch next warp-tile into registers (overlaps FFMAs) ----
        float r[6];
        const int next = wt + NW;
        if (next < NTT) stage_to_regs(next, r);

        // ---- compute: 14 quads x (LDS.128 + FFMA-imm), zero taps elided ----
        float acc[NEW_SR] = {0.f, 0.f, 0.f, 0.f, 0.f};
        const float4* w4 =
            reinterpret_cast<const float4*>(&sw[wid][cur][OLD_SR * lane]);
        #pragma unroll
        for (int q = 0; q < KSZ / 4; ++q) {
            const float4 xv = w4[q];
            #pragma unroll
            for (int i = 0; i < NEW_SR; ++i) {
                if ((float)KT.c[i][4*q+0] != 0.0f)
                    acc[i] = fmaf(xv.x, (float)KT.c[i][4*q+0], acc[i]);
                if ((float)KT.c[i][4*q+1] != 0.0f)
                    acc[i] = fmaf(xv.y, (float)KT.c[i][4*q+1], acc[i]);
                if ((float)KT.c[i][4*q+2] != 0.0f)
                    acc[i] = fmaf(xv.z, (float)KT.c[i][4*q+2], acc[i]);
                if ((float)KT.c[i][4*q+3] != 0.0f)
                    acc[i] = fmaf(xv.w, (float)KT.c[i][4*q+3], acc[i]);
            }
        }

        // ---- store 5 interleaved phases (warp covers 640B contiguous) ----
        {
            const int b  = wt >> 13;
            const int tw = wt & (TPW - 1);
            const int n  = tw * WN + lane;
            float* o = out + (size_t)b * Orow + (size_t)NEW_SR * (size_t)n;
            #pragma unroll
            for (int i = 0; i < NEW_SR; ++i) o[i] = acc[i];
        }

        // ---- commit prefetch to the other private buffer; warp-local sync ----
        if (next < NTT) {
            commit(cur ^ 1, r);
            __syncwarp();
        }
    }
}

extern "C" void kernel_launch(void* const* d_in, const int* in_sizes, int n_in,
                              void* d_out, int out_size)
{
    const float* x = (const float*)d_in[0];
    int xs = in_sizes[0];
    // Defensive: if input order is (kernel, x), swap (coeffs are baked in).
    if (n_in >= 2 && in_sizes[0] == NEW_SR * KSZ) {
        x  = (const float*)d_in[1];
        xs = in_sizes[1];
    }
    const int B = 32;
    const int T = xs / B;     // 1048576
    resample_kernel<<<NCTAS, THREADS>>>(x, (float*)d_out, T);
}

// round 14
// speedup vs baseline: 1.2639x; 1.1204x over previous
#include <cuda_runtime.h>
#include <cstdint>

#define OLD_SR 4
#define NEW_SR 5
#define KSZ    56            // taps per phase
#define WIDTH  26            // left pad (edge replicate)
#define THREADS 256
#define NWARPS 8
#define WN     64            // n-groups per warp-tile (2 per lane)
#define WLOAD  (OLD_SR * WN + KSZ - 4)  // 308 staged floats (units 0..76)
#define PSTR   176           // parity-array stride in floats (bank-staggered)
#define NCTAS  740           // 148 x 5 resident CTAs
#define NSTREAM (NCTAS * NWARPS)        // 5920 warp streams
#define TPW    4096          // warp-tiles per row = 262144 / 64
#define SPR    (NSTREAM / 32)           // 185 streams per row

// ---------------------------------------------------------------------------
// Compile-time polyphase table (double-only constexpr; (float) cast at the
// use site folds to a float literal -> SASS FFMA R,R,IMM,R, rt_SMSP=1).
// ---------------------------------------------------------------------------
constexpr double D_PI      = 3.141592653589793;
constexpr double TWO_OV_PI = 0.6366197723675814;
constexpr double PIO2_HI   = 1.5707963267948966;
constexpr double PIO2_LO   = 6.123233995736766e-17;

constexpr double poly_sin(double y) {
    double y2 = y * y;
    return y * (1.0 + y2 * (-1.0/6 + y2 * (1.0/120 + y2 * (-1.0/5040
             + y2 * (1.0/362880 + y2 * (-1.0/39916800
             + y2 * (1.0/6227020800.0 - y2 * (1.0/1307674368000.0))))))));
}
constexpr double poly_cos(double y) {
    double y2 = y * y;
    return 1.0 + y2 * (-0.5 + y2 * (1.0/24 + y2 * (-1.0/720
             + y2 * (1.0/40320 + y2 * (-1.0/3628800
             + y2 * (1.0/479001600.0 - y2 * (1.0/87178291200.0)))))));
}
constexpr int red_m(double x, double& y) {
    double q = x * TWO_OV_PI;
    int k = (int)(q + (q >= 0 ? 0.5 : -0.5));
    y = (x - k * PIO2_HI) - k * PIO2_LO;
    int m = k % 4; if (m < 0) m += 4;
    return m;
}
constexpr double ksin(double x) {
    double y = 0.0; int m = red_m(x, y);
    return (m == 0) ? poly_sin(y) : (m == 1) ? poly_cos(y)
         : (m == 2) ? -poly_sin(y) : -poly_cos(y);
}
constexpr double kcos(double x) {
    double y = 0.0; int m = red_m(x, y);
    return (m == 0) ? poly_cos(y) : (m == 1) ? -poly_sin(y)
         : (m == 2) ? -poly_cos(y) : poly_sin(y);
}
struct KTabD {
    double c[NEW_SR][KSZ];
    constexpr KTabD() : c{} {
        for (int i = 0; i < NEW_SR; ++i) {
            double s = 0.0;
            for (int j = 0; j < KSZ; ++j) {
                double t = (-(double)i / 5.0 + (double)(j - WIDTH) / 4.0)
                         * (4.0 * 0.945);
                if (t > 24.0) t = 24.0;
                if (t < -24.0) t = -24.0;
                t *= D_PI;
                double snc = (t == 0.0) ? 1.0 : ksin(t) / t;
                double w = kcos(t / 48.0);
                double v = snc * w * w;
                c[i][j] = v; s += v;
            }
            for (int j = 0; j < KSZ; ++j) c[i][j] = c[i][j] / s;
        }
    }
};

__global__ __launch_bounds__(THREADS, 5)
void resample_kernel(const float* __restrict__ x,
                     float* __restrict__ out, int T)
{
    constexpr KTabD KT{};
    // Per-warp private double buffer, de-interleaved by 16B-unit parity.
    // [warp][buf][parity][PSTR]; PSTR=176 staggers O by 16 banks vs E.
    __shared__ __align__(16) float sx[NWARPS][2][2][PSTR];

    const int lane = threadIdx.x & 31;
    const int wid  = threadIdx.x >> 5;

    // Stream -> (row, starting tile). One division, loop is row-local.
    const int s  = blockIdx.x * NWARPS + wid;
    const int r  = s / SPR;
    const int k0 = s - r * SPR;
    const float* xrow = x + (size_t)r * (size_t)T;
    float* orow = out + (size_t)r * (size_t)NEW_SR * (size_t)(T / OLD_SR);

    auto stage_to_regs = [&](int tw, float rg[10]) {
        const int base_j = OLD_SR * WN * tw - WIDTH;   // 256*tw - 26
        if (tw != 0 && tw != TPW - 1) {                // interior: no clamps
            #pragma unroll
            for (int k = 0; k < 10; ++k) {
                int idx = lane + 32 * k;
                if (idx < WLOAD) rg[k] = xrow[base_j + idx];
            }
        } else {                                        // row edges: clamp
            #pragma unroll
            for (int k = 0; k < 10; ++k) {
                int idx = lane + 32 * k;
                if (idx < WLOAD) {
                    int j = base_j + idx;
                    j = j < 0 ? 0 : (j > T - 1 ? T - 1 : j);
                    rg[k] = xrow[j];
                }
            }
        }
    };
    // De-interleave: unit u = idx>>2 -> parity u&1, pos (u>>1)*4 + (idx&3).
    auto commit = [&](int buf, const float rg[10]) {
        #pragma unroll
        for (int k = 0; k < 10; ++k) {
            int idx = lane + 32 * k;
            if (idx < WLOAD) {
                int u = idx >> 2;
                sx[wid][buf][u & 1][((u >> 1) << 2) | (idx & 3)] = rg[k];
            }
        }
    };

    {
        float rg[10];
        stage_to_regs(k0, rg);
        commit(0, rg);
    }
    __syncwarp();

    int cur = 0;
    #pragma unroll 1
    for (int tw = k0; tw < TPW; tw += SPR, cur ^= 1) {
        // ---- prefetch next warp-tile (overlaps the FFMA block) ----
        float rg[10];
        const int next = tw + SPR;
        if (next < TPW) stage_to_regs(next, rg);

        // ---- compute 2 consecutive n per lane: 15 quads feed both ----
        float a0[NEW_SR] = {0.f,0.f,0.f,0.f,0.f};
        float a1[NEW_SR] = {0.f,0.f,0.f,0.f,0.f};
        const float4* e4 = reinterpret_cast<const float4*>(&sx[wid][cur][0][0]) + lane;
        const float4* o4 = reinterpret_cast<const float4*>(&sx[wid][cur][1][0]) + lane;
        #pragma unroll
        for (int q = 0; q <= 14; ++q) {
            const float4 xv = (q & 1) ? o4[(q - 1) >> 1] : e4[q >> 1];
            const float e0 = xv.x, e1 = xv.y, e2 = xv.z, e3 = xv.w;
            if (q <= 13) {           // n0: taps 4q..4q+3
                #pragma unroll
                for (int i = 0; i < NEW_SR; ++i) {
                    if ((float)KT.c[i][4*q+0] != 0.0f) a0[i] = fmaf(e0, (float)KT.c[i][4*q+0], a0[i]);
                    if ((float)KT.c[i][4*q+1] != 0.0f) a0[i] = fmaf(e1, (float)KT.c[i][4*q+1], a0[i]);
                    if ((float)KT.c[i][4*q+2] != 0.0f) a0[i] = fmaf(e2, (float)KT.c[i][4*q+2], a0[i]);
                    if ((float)KT.c[i][4*q+3] != 0.0f) a0[i] = fmaf(e3, (float)KT.c[i][4*q+3], a0[i]);
                }
            }
            if (q >= 1) {            // n1 = n0+1: taps 4(q-1)..4(q-1)+3
                const int p = 4 * (q - 1);
                #pragma unroll
                for (int i = 0; i < NEW_SR; ++i) {
                    if ((float)KT.c[i][p+0] != 0.0f) a1[i] = fmaf(e0, (float)KT.c[i][p+0], a1[i]);
                    if ((float)KT.c[i][p+1] != 0.0f) a1[i] = fmaf(e1, (float)KT.c[i][p+1], a1[i]);
                    if ((float)KT.c[i][p+2] != 0.0f) a1[i] = fmaf(e2, (float)KT.c[i][p+2], a1[i]);
                    if ((float)KT.c[i][p+3] != 0.0f) a1[i] = fmaf(e3, (float)KT.c[i][p+3], a1[i]);
                }
            }
        }

        // ---- store 10 contiguous floats as 5 STG.64 (warp: 1280B) ----
        {
            float2* o = reinterpret_cast<float2*>(
                orow + (size_t)(NEW_SR * WN) * (size_t)tw + 10 * lane);
            o[0] = make_float2(a0[0], a0[1]);
            o[1] = make_float2(a0[2], a0[3]);
            o[2] = make_float2(a0[4], a1[0]);
            o[3] = make_float2(a1[1], a1[2]);
            o[4] = make_float2(a1[3], a1[4]);
        }

        // ---- commit prefetch to the other private buffer; warp sync ----
        if (next < TPW) {
            commit(cur ^ 1, rg);
            __syncwarp();
        }
    }
}

extern "C" void kernel_launch(void* const* d_in, const int* in_sizes, int n_in,
                              void* d_out, int out_size)
{
    const float* x = (const float*)d_in[0];
    int xs = in_sizes[0];
    // Defensive: if input order is (kernel, x), swap (coeffs are baked in).
    if (n_in >= 2 && in_sizes[0] == NEW_SR * KSZ) {
        x  = (const float*)d_in[1];
        xs = in_sizes[1];
    }
    const int B = 32;
    const int T = xs / B;     // 1048576
    resample_kernel<<<NCTAS, THREADS>>>(x, (float*)d_out, T);
}

// round 15
// speedup vs baseline: 1.3342x; 1.0556x over previous
#include <cuda_runtime.h>
#include <cstdint>

#define OLD_SR 4
#define NEW_SR 5
#define KSZ    56            // taps per phase
#define WIDTH  26            // left pad (edge replicate)
#define THREADS 256
#define NWARPS 8
#define NPT    4             // consecutive n per lane
#define WN     128           // n per warp-tile
#define NUNITS 142           // staged 16B units per tile (568 floats)
#define PSTR   148           // per-array stride in floats (mult of 4, >=144)
#define NCTAS  740           // 148 SMs x 5 resident CTAs
#define NSTREAM (NCTAS * NWARPS)       // 5920 warp streams
#define TPW    2048          // warp-tiles per row = 262144 / 128
#define NTT    (32 * TPW)    // 65536 warp-tiles total

// ---------------------------------------------------------------------------
// Compile-time polyphase table (double-only constexpr; (float) cast at the
// use site folds to a float literal -> SASS FFMA R,R,IMM,R, rt_SMSP=1).
// ---------------------------------------------------------------------------
constexpr double D_PI      = 3.141592653589793;
constexpr double TWO_OV_PI = 0.6366197723675814;
constexpr double PIO2_HI   = 1.5707963267948966;
constexpr double PIO2_LO   = 6.123233995736766e-17;

constexpr double poly_sin(double y) {
    double y2 = y * y;
    return y * (1.0 + y2 * (-1.0/6 + y2 * (1.0/120 + y2 * (-1.0/5040
             + y2 * (1.0/362880 + y2 * (-1.0/39916800
             + y2 * (1.0/6227020800.0 - y2 * (1.0/1307674368000.0))))))));
}
constexpr double poly_cos(double y) {
    double y2 = y * y;
    return 1.0 + y2 * (-0.5 + y2 * (1.0/24 + y2 * (-1.0/720
             + y2 * (1.0/40320 + y2 * (-1.0/3628800
             + y2 * (1.0/479001600.0 - y2 * (1.0/87178291200.0)))))));
}
constexpr int red_m(double x, double& y) {
    double q = x * TWO_OV_PI;
    int k = (int)(q + (q >= 0 ? 0.5 : -0.5));
    y = (x - k * PIO2_HI) - k * PIO2_LO;
    int m = k % 4; if (m < 0) m += 4;
    return m;
}
constexpr double ksin(double x) {
    double y = 0.0; int m = red_m(x, y);
    return (m == 0) ? poly_sin(y) : (m == 1) ? poly_cos(y)
         : (m == 2) ? -poly_sin(y) : -poly_cos(y);
}
constexpr double kcos(double x) {
    double y = 0.0; int m = red_m(x, y);
    return (m == 0) ? poly_cos(y) : (m == 1) ? -poly_sin(y)
         : (m == 2) ? -poly_cos(y) : poly_sin(y);
}
struct KTabD {
    double c[NEW_SR][KSZ];
    constexpr KTabD() : c{} {
        for (int i = 0; i < NEW_SR; ++i) {
            double s = 0.0;
            for (int j = 0; j < KSZ; ++j) {
                double t = (-(double)i / 5.0 + (double)(j - WIDTH) / 4.0)
                         * (4.0 * 0.945);
                if (t > 24.0) t = 24.0;
                if (t < -24.0) t = -24.0;
                t *= D_PI;
                double snc = (t == 0.0) ? 1.0 : ksin(t) / t;
                double w = kcos(t / 48.0);
                double v = snc * w * w;
                c[i][j] = v; s += v;
            }
            for (int j = 0; j < KSZ; ++j) c[i][j] = c[i][j] / s;
        }
    }
};

__global__ __launch_bounds__(THREADS, 5)
void resample_kernel(const float* __restrict__ x,
                     float* __restrict__ out, int T)
{
    constexpr KTabD KT{};
    // Per-warp private double buffer, 4-way de-interleaved by 16B-chunk
    // index mod 4: chunk h -> sx[w][buf][h&3][(h>>2)*4 .. +3].
    __shared__ __align__(16) float sx[NWARPS][2][4][PSTR];

    const int lane = threadIdx.x & 31;
    const int wid  = threadIdx.x >> 5;
    const size_t Orow = (size_t)NEW_SR * (size_t)(T / OLD_SR);

    // Stage: load aligned superset [B0-2, B0+566), B0 = 512*tw - 26.
    auto stage_vec = [&](int wt, float4 v[5]) {
        const int b  = wt >> 11;                 // TPW = 2048
        const int tw = wt & (TPW - 1);
        const float4* g = reinterpret_cast<const float4*>(
            x + (size_t)b * (size_t)T + (512 * tw - 28));
        #pragma unroll
        for (int k = 0; k < 5; ++k) {
            int m = lane + 32 * k;
            if (m < NUNITS) v[k] = __ldg(g + m);
        }
    };
    auto stage_edge = [&](int wt, float4 v[5]) {  // tw==0 / tw==TPW-1: clamp
        const int b  = wt >> 11;
        const int tw = wt & (TPW - 1);
        const float* xr = x + (size_t)b * (size_t)T;
        const int base = 512 * tw - 28;
        #pragma unroll
        for (int k = 0; k < 5; ++k) {
            int m = lane + 32 * k;
            if (m < NUNITS) {
                float tmp[4];
                #pragma unroll
                for (int c = 0; c < 4; ++c) {
                    int j = base + 4 * m + c;
                    j = j < 0 ? 0 : (j > T - 1 ? T - 1 : j);
                    tmp[c] = xr[j];
                }
                v[k] = make_float4(tmp[0], tmp[1], tmp[2], tmp[3]);
            }
        }
    };
    // Scatter: reg m holds window floats 4m-2..4m+1; (x,y)->chunk m-1
    // slots 2,3; (z,w)->chunk m slots 0,1. Both STS.64, 8B-aligned.
    auto commit = [&](int buf, const float4 v[5]) {
        #pragma unroll
        for (int k = 0; k < 5; ++k) {
            int m = lane + 32 * k;
            if (m >= 1 && m < NUNITS) {
                int h = m - 1;
                *reinterpret_cast<float2*>(
                    &sx[wid][buf][h & 3][((h >> 2) << 2) + 2]) =
                    make_float2(v[k].x, v[k].y);
            }
            if (m <= 140) {
                *reinterpret_cast<float2*>(
                    &sx[wid][buf][m & 3][(m >> 2) << 2]) =
                    make_float2(v[k].z, v[k].w);
            }
        }
    };

    int wt = blockIdx.x * NWARPS + wid;
    {
        float4 v[5];
        const int tw0 = wt & (TPW - 1);
        if (tw0 == 0 || tw0 == TPW - 1) stage_edge(wt, v);
        else                            stage_vec(wt, v);
        commit(0, v);
    }
    __syncwarp();

    int cur = 0;
    #pragma unroll 1
    for (; wt < NTT; wt += NSTREAM, cur ^= 1) {
        // ---- prefetch + commit next tile first (regs freed before FFMAs;
        //      LDG->STS latency absorbed by the other warps) ----
        const int next = wt + NSTREAM;
        if (next < NTT) {
            float4 v[5];
            const int twn = next & (TPW - 1);
            if (twn == 0 || twn == TPW - 1) stage_edge(next, v);
            else                            stage_vec(next, v);
            commit(cur ^ 1, v);
        }

        // ---- compute 4 consecutive n: 17 chunk-quads feed all windows ----
        // chunk h = 4*lane + q lives at sx[w][cur][q&3][(lane + (q>>2))*16B]
        float acc[NPT][NEW_SR];
        #pragma unroll
        for (int j = 0; j < NPT; ++j)
            #pragma unroll
            for (int i = 0; i < NEW_SR; ++i) acc[j][i] = 0.f;

        #pragma unroll
        for (int q = 0; q <= 16; ++q) {
            const float4 xv = *(reinterpret_cast<const float4*>(
                &sx[wid][cur][q & 3][0]) + (lane + (q >> 2)));
            const float e0 = xv.x, e1 = xv.y, e2 = xv.z, e3 = xv.w;
            #pragma unroll
            for (int j = 0; j < NPT; ++j) {
                const int m = q - j;           // tap quad index for output j
                if (m >= 0 && m <= 13) {
                    #pragma unroll
                    for (int i = 0; i < NEW_SR; ++i) {
                        if ((float)KT.c[i][4*m+0] != 0.0f) acc[j][i] = fmaf(e0, (float)KT.c[i][4*m+0], acc[j][i]);
                        if ((float)KT.c[i][4*m+1] != 0.0f) acc[j][i] = fmaf(e1, (float)KT.c[i][4*m+1], acc[j][i]);
                        if ((float)KT.c[i][4*m+2] != 0.0f) acc[j][i] = fmaf(e2, (float)KT.c[i][4*m+2], acc[j][i]);
                        if ((float)KT.c[i][4*m+3] != 0.0f) acc[j][i] = fmaf(e3, (float)KT.c[i][4*m+3], acc[j][i]);
                    }
                }
            }
        }

        // ---- store 20 contiguous floats as 5 STG.128 (warp: 2560B) ----
        {
            const int b  = wt >> 11;
            const int tw = wt & (TPW - 1);
            float4* o = reinterpret_cast<float4*>(
                out + (size_t)b * Orow + (size_t)(NEW_SR * WN) * (size_t)tw
                    + 20 * lane);
            o[0] = make_float4(acc[0][0], acc[0][1], acc[0][2], acc[0][3]);
            o[1] = make_float4(acc[0][4], acc[1][0], acc[1][1], acc[1][2]);
            o[2] = make_float4(acc[1][3], acc[1][4], acc[2][0], acc[2][1]);
            o[3] = make_float4(acc[2][2], acc[2][3], acc[2][4], acc[3][0]);
            o[4] = make_float4(acc[3][1], acc[3][2], acc[3][3], acc[3][4]);
        }

        __syncwarp();   // commit(cur^1) visible before next iter's reads
    }
}

extern "C" void kernel_launch(void* const* d_in, const int* in_sizes, int n_in,
                              void* d_out, int out_size)
{
    const float* x = (const float*)d_in[0];
    int xs = in_sizes[0];
    // Defensive: if input order is (kernel, x), swap (coeffs are baked in).
    if (n_in >= 2 && in_sizes[0] == NEW_SR * KSZ) {
        x  = (const float*)d_in[1];
        xs = in_sizes[1];
    }
    const int B = 32;
    const int T = xs / B;     // 1048576
    resample_kernel<<<NCTAS, THREADS>>>(x, (float*)d_out, T);
}